// round 12
// baseline (speedup 1.0000x reference)
#include <cuda_runtime.h>
#include <math.h>

// ---------------------------------------------------------------------------
// Decoder_50775103373422: 2-layer LSTM (B=64, H=2048, IN=OUT=66, T=25) with
// hardtanh output fed back as next input.
// R12: 8-way k-split at 256 threads (2 warps/SMSP for latency hiding, while
//      keeping the R11 minimum of 32KB LDS reads per tile); fc grid (64,3).
// ---------------------------------------------------------------------------

namespace {
constexpr int B_   = 64;    // batch
constexpr int H_   = 2048;  // hidden
constexpr int IN_  = 66;    // input / output features
constexpr int T_   = 25;    // timesteps
constexpr int XPAD = 72;    // padded input width (multiple of 8)
constexpr int JT   = 16;    // hidden units per CTA  -> grid = 2048/16 = 128
constexpr int SLD  = 76;    // smem row stride in floats (conflict-free)
constexpr int NTH  = 256;   // threads per cell CTA (8 warps, 8-way k-split)
constexpr int STG  = 3;     // cp.async pipeline stages
constexpr int TILE_WORDS = B_ * SLD;                       // floats per A or B stage
constexpr int SMEM_BYTES = STG * 2 * TILE_WORDS * 4;       // 116736 B dynamic smem
constexpr int GPITCH = 64 * 65 + 16;                       // reduce-buffer pitch (floats)
}

// Scratch state (allocation-free rule: __device__ globals), 16B-aligned
__device__ __align__(16) float g_x[2][B_][XPAD];   // fed-back input, ping-pong
__device__ __align__(16) float g_h[2][2][B_][H_];  // [layer][parity][b][j]
__device__ __align__(16) float g_c[2][B_][H_];     // in-place per launch

__device__ __forceinline__ unsigned u32smem(const void* p) {
    return (unsigned)__cvta_generic_to_shared(p);
}
__device__ __forceinline__ void cpasync16(unsigned s, const void* g) {
    asm volatile("cp.async.cg.shared.global [%0], [%1], 16;\n" :: "r"(s), "l"(g));
}
__device__ __forceinline__ void cpcommit() {
    asm volatile("cp.async.commit_group;\n" ::);
}
template <int N>
__device__ __forceinline__ void cpwait() {
    asm volatile("cp.async.wait_group %0;\n" :: "n"(N));
}

__device__ __forceinline__ void mma8(float* d,
                                     unsigned a0, unsigned a1, unsigned a2, unsigned a3,
                                     unsigned b0, unsigned b1) {
    asm volatile(
        "mma.sync.aligned.m16n8k8.row.col.f32.tf32.tf32.f32 "
        "{%0,%1,%2,%3}, {%4,%5,%6,%7}, {%8,%9}, {%0,%1,%2,%3};"
        : "+f"(d[0]), "+f"(d[1]), "+f"(d[2]), "+f"(d[3])
        : "r"(a0), "r"(a1), "r"(a2), "r"(a3), "r"(b0), "r"(b1));
}

// Issue cp.async for one 64x64 fp32 tile of A and of B into a stage (256 thr).
__device__ __forceinline__ void issue_tile(float* sA, float* sB,
                                           const float* __restrict__ A,
                                           const float* __restrict__ W,
                                           int j0, int k0, int tid) {
    const int r = tid >> 4;            // 0..15
    const int c = (tid & 15) << 2;     // 0..60
#pragma unroll
    for (int p = 0; p < 4; p++) {
        int row = r + p * 16;
        cpasync16(u32smem(sA + row * SLD + c), A + (size_t)row * H_ + k0 + c);
    }
#pragma unroll
    for (int p = 0; p < 4; p++) {
        int n = r + p * 16;
        int R = (n >> 4) * H_ + j0 + (n & 15);   // gate-major weight row
        cpasync16(u32smem(sB + n * SLD + c), W + (size_t)R * H_ + k0 + c);
    }
}

// Warp computes ONE k8 slice (kk = elements [kk, kk+8)) of a tile, full
// m64 x n64 output. As/Bs hold raw fp32 bits; HMMA.TF32 truncates in HW.
__device__ __forceinline__ void tile_kb(const unsigned* __restrict__ As,
                                        const unsigned* __restrict__ Bs,
                                        float (&acc)[4][8][4],
                                        int kk, int gID, int tig) {
    unsigned a[4][4];
#pragma unroll
    for (int am = 0; am < 4; am++) {
        int r0 = (am * 16 + gID) * SLD;
        a[am][0] = As[r0 + kk + tig];
        a[am][1] = As[r0 + 8 * SLD + kk + tig];
        a[am][2] = As[r0 + kk + tig + 4];
        a[am][3] = As[r0 + 8 * SLD + kk + tig + 4];
    }
#pragma unroll
    for (int t8 = 0; t8 < 8; t8++) {
        int n = (t8 * 8 + gID) * SLD;
        unsigned b0 = Bs[n + kk + tig];
        unsigned b1 = Bs[n + kk + tig + 4];
#pragma unroll
        for (int am = 0; am < 4; am++)
            mma8(acc[am][t8], a[am][0], a[am][1], a[am][2], a[am][3], b0, b1);
    }
}

// One LSTM cell step for one layer. CTA owns hidden units [j0, j0+16) across
// all 4 gates (64 N-cols), full batch (M=64). 8 warps split each tile's K
// 8-way; epilogue reduces 8 partial m64n64 grids and does the cell update.
__global__ void __launch_bounds__(NTH, 1)
lstm_cell_kernel(const float* __restrict__ Wih, const float* __restrict__ Whh,
                 const float* __restrict__ bih, const float* __restrict__ bhh,
                 int layer, int parity, int use_x) {
    extern __shared__ __align__(16) float smem_raw[];
    float* sA[STG];
    float* sB[STG];
#pragma unroll
    for (int st = 0; st < STG; st++) {
        sA[st] = smem_raw + st * 2 * TILE_WORDS;
        sB[st] = sA[st] + TILE_WORDS;
    }

    const int tid  = threadIdx.x;
    const int j0   = blockIdx.x * JT;
    const int warp = tid >> 5, lane = tid & 31;
    const int gID = lane >> 2, tig = lane & 3;
    const int mykk = warp * 8;          // this warp's k8 slice of every tile

    float acc[4][8][4];
#pragma unroll
    for (int a = 0; a < 4; a++)
#pragma unroll
        for (int b = 0; b < 8; b++)
#pragma unroll
            for (int c = 0; c < 4; c++) acc[a][b][c] = 0.f;

    // ---- layer0 only: x @ Wih0^T  (K=72: 9 k8 slices; warp 7 takes the 9th) ----
    if (use_x) {
        const float* A = &g_x[parity][0][0];
        for (int idx = tid; idx < B_ * XPAD; idx += NTH) {
            int r = idx / XPAD, k = idx - r * XPAD;
            sA[0][r * SLD + k] = A[idx];
        }
        for (int idx = tid; idx < B_ * XPAD; idx += NTH) {
            int n = idx / XPAD, k = idx - n * XPAD;
            int R = (n >> 4) * H_ + j0 + (n & 15);
            sB[0][n * SLD + k] = (k < IN_) ? Wih[R * IN_ + k] : 0.f;
        }
        __syncthreads();
        tile_kb((const unsigned*)sA[0], (const unsigned*)sB[0], acc, mykk, gID, tig);
        if (warp == 7)
            tile_kb((const unsigned*)sA[0], (const unsigned*)sB[0], acc, 64, gID, tig);
        __syncthreads();
    }

    // ---- K=2048 segments, 3-stage cp.async pipeline ----
    const float* Aseg[2];
    const float* Wseg[2];
    int nseg;
    if (use_x) {                                 // layer 0: h0_prev @ Whh0^T
        Aseg[0] = &g_h[0][parity][0][0];     Wseg[0] = Whh;  nseg = 1;
    } else {                                     // layer 1: h0_new @ Wih1^T + h1_prev @ Whh1^T
        Aseg[0] = &g_h[0][parity ^ 1][0][0]; Wseg[0] = Wih;
        Aseg[1] = &g_h[1][parity][0][0];     Wseg[1] = Whh;
        nseg = 2;
    }
    const int total = nseg * 32;

    // Prologue: fill STG-1 stages.
#pragma unroll
    for (int s = 0; s < STG - 1; s++) {
        issue_tile(sA[s], sB[s], Aseg[s >> 5], Wseg[s >> 5], j0, (s & 31) * 64, tid);
        cpcommit();
    }

    for (int s = 0; s < total; s++) {
        cpwait<STG - 2>();          // stage s landed
        __syncthreads();
        int nx = s + STG - 1;
        if (nx < total) {
            issue_tile(sA[nx % STG], sB[nx % STG],
                       Aseg[nx >> 5], Wseg[nx >> 5], j0, (nx & 31) * 64, tid);
        }
        cpcommit();                 // keep group accounting aligned
        int cs = s % STG;
        tile_kb((const unsigned*)sA[cs], (const unsigned*)sB[cs], acc, mykk, gID, tig);
    }
    __syncthreads();

    // ---- epilogue: 8 partial grids -> 4 buffers (store/add), then update ----
    float* G0 = smem_raw;
    float* G1 = smem_raw + GPITCH;
    float* G2 = smem_raw + 2 * GPITCH;
    float* G3 = smem_raw + 3 * GPITCH;
    float* Gw = smem_raw + (warp & 3) * GPITCH;
    if (warp < 4) {
#pragma unroll
        for (int am = 0; am < 4; am++)
#pragma unroll
            for (int t8 = 0; t8 < 8; t8++) {
                int r0 = am * 16 + gID;
                int n  = t8 * 8 + (tig << 1);
                Gw[n * 65 + r0]           = acc[am][t8][0];
                Gw[(n + 1) * 65 + r0]     = acc[am][t8][1];
                Gw[n * 65 + r0 + 8]       = acc[am][t8][2];
                Gw[(n + 1) * 65 + r0 + 8] = acc[am][t8][3];
            }
    }
    __syncthreads();
    if (warp >= 4) {
#pragma unroll
        for (int am = 0; am < 4; am++)
#pragma unroll
            for (int t8 = 0; t8 < 8; t8++) {
                int r0 = am * 16 + gID;
                int n  = t8 * 8 + (tig << 1);
                Gw[n * 65 + r0]           += acc[am][t8][0];
                Gw[(n + 1) * 65 + r0]     += acc[am][t8][1];
                Gw[n * 65 + r0 + 8]       += acc[am][t8][2];
                Gw[(n + 1) * 65 + r0 + 8] += acc[am][t8][3];
            }
    }
    __syncthreads();

    float* c_io  = &g_c[layer][0][0];
    float* h_out = &g_h[layer][parity ^ 1][0][0];
#pragma unroll
    for (int i = 0; i < 4; i++) {
        int idx = tid + i * NTH;   // 0..1023
        int jn  = idx & 15;
        int b   = idx >> 4;
        int j   = j0 + jn;
        int pi = jn * 65 + b;
        int pf = (16 + jn) * 65 + b;
        int pg = (32 + jn) * 65 + b;
        int po = (48 + jn) * 65 + b;
        float gi = G0[pi] + G1[pi] + G2[pi] + G3[pi] + bih[j]          + bhh[j];
        float gf = G0[pf] + G1[pf] + G2[pf] + G3[pf] + bih[H_ + j]     + bhh[H_ + j];
        float gc = G0[pg] + G1[pg] + G2[pg] + G3[pg] + bih[2 * H_ + j] + bhh[2 * H_ + j];
        float go = G0[po] + G1[po] + G2[po] + G3[po] + bih[3 * H_ + j] + bhh[3 * H_ + j];
        float ii = 1.f / (1.f + expf(-gi));
        float ff = 1.f / (1.f + expf(-gf));
        float gt = tanhf(gc);
        float oo = 1.f / (1.f + expf(-go));
        int   ci = b * H_ + j;
        float c2 = ff * c_io[ci] + ii * gt;
        c_io[ci]  = c2;
        h_out[ci] = oo * tanhf(c2);
    }
}

// FC + hardtanh + feedback. Grid (64 b, 3 ng) x 256 thr: 192 CTAs for SM
// parallelism; h[b] staged in smem; warps sweep 22 outputs with lanes
// striding K -> coalesced fcw reads (L2-resident).
__global__ void __launch_bounds__(256, 1)
fc_kernel(const float* __restrict__ fcw, const float* __restrict__ fcb,
          float* __restrict__ out, int hpar, int t) {
    __shared__ __align__(16) float hs[H_];
    const int b  = blockIdx.x;
    const int n0 = blockIdx.y * 22;
    for (int k = threadIdx.x * 8; k < H_; k += 256 * 8) {
        *reinterpret_cast<float4*>(&hs[k]) =
            *reinterpret_cast<const float4*>(&g_h[1][hpar][b][k]);
        *reinterpret_cast<float4*>(&hs[k + 4]) =
            *reinterpret_cast<const float4*>(&g_h[1][hpar][b][k + 4]);
    }
    __syncthreads();

    const int warp = threadIdx.x >> 5, lane = threadIdx.x & 31;
    for (int nn = warp; nn < 22; nn += 8) {
        int n = n0 + nn;
        const float* w = fcw + (size_t)n * H_;
        float s = 0.f;
#pragma unroll
        for (int i = 0; i < 16; i++) {
            int k = i * 128 + lane * 4;
            float4 wv = *reinterpret_cast<const float4*>(w + k);
            float4 hv = *reinterpret_cast<const float4*>(hs + k);
            s += wv.x * hv.x + wv.y * hv.y + wv.z * hv.z + wv.w * hv.w;
        }
        s += __shfl_xor_sync(0xffffffffu, s, 16);
        s += __shfl_xor_sync(0xffffffffu, s, 8);
        s += __shfl_xor_sync(0xffffffffu, s, 4);
        s += __shfl_xor_sync(0xffffffffu, s, 2);
        s += __shfl_xor_sync(0xffffffffu, s, 1);
        if (lane == 0) {
            float r = s + fcb[n];
            r = fminf(1.f, fmaxf(-1.f, r));          // hardtanh
            out[(b * T_ + t) * IN_ + n] = r;         // d_out[b][t][n]
            g_x[hpar][b][n] = r;                     // detached feedback
        }
    }
}

// Copy inputs into scratch each launch (determinism: c is updated in place).
__global__ void init_kernel(const float* __restrict__ inputs,
                            const float* __restrict__ hiddens,
                            const float* __restrict__ cells) {
    const int stride = gridDim.x * blockDim.x;
    const int tid0   = blockIdx.x * blockDim.x + threadIdx.x;
    for (int i = tid0; i < 2 * B_ * XPAD; i += stride) {
        int par = i / (B_ * XPAD);
        int rem = i - par * (B_ * XPAD);
        int b = rem / XPAD, k = rem - b * XPAD;
        (&g_x[0][0][0])[i] = (par == 0 && k < IN_) ? inputs[b * IN_ + k] : 0.f;
    }
    for (int i = tid0; i < 2 * B_ * H_; i += stride) {
        int l   = i >> 17;               // B_*H_ = 2^17
        int rem = i & (B_ * H_ - 1);
        (&g_h[l][0][0][0])[rem] = hiddens[i];
        (&g_c[0][0][0])[i]      = cells[i];
    }
}

extern "C" void kernel_launch(void* const* d_in, const int* in_sizes, int n_in,
                              void* d_out, int out_size) {
    const float* inputs  = (const float*)d_in[0];
    const float* hiddens = (const float*)d_in[1];
    const float* cells   = (const float*)d_in[2];
    const float* Wih0 = (const float*)d_in[3];
    const float* Whh0 = (const float*)d_in[4];
    const float* bih0 = (const float*)d_in[5];
    const float* bhh0 = (const float*)d_in[6];
    const float* Wih1 = (const float*)d_in[7];
    const float* Whh1 = (const float*)d_in[8];
    const float* bih1 = (const float*)d_in[9];
    const float* bhh1 = (const float*)d_in[10];
    const float* fcw  = (const float*)d_in[11];
    const float* fcb  = (const float*)d_in[12];
    float* out = (float*)d_out;

    // Opt in to >48KB dynamic smem (idempotent, capture-safe host call).
    cudaFuncSetAttribute(lstm_cell_kernel,
                         cudaFuncAttributeMaxDynamicSharedMemorySize, SMEM_BYTES);

    init_kernel<<<256, 256>>>(inputs, hiddens, cells);
    dim3 fc_grid(B_, 3);
    for (int t = 0; t < T_; t++) {
        int p = t & 1;
        lstm_cell_kernel<<<H_ / JT, NTH, SMEM_BYTES>>>(Wih0, Whh0, bih0, bhh0, 0, p, 1);
        lstm_cell_kernel<<<H_ / JT, NTH, SMEM_BYTES>>>(Wih1, Whh1, bih1, bhh1, 1, p, 0);
        fc_kernel<<<fc_grid, 256>>>(fcw, fcb, out, p ^ 1, t);
    }
}